// round 16
// baseline (speedup 1.0000x reference)
#include <cuda_runtime.h>
#include <cuda_bf16.h>
#include <math.h>

#define VOCAB   128
#define HIDDEN  1024
#define BATCH   64
#define SEQ     512

#define RSTRIDE 520    // reduce-buffer warp stride (floats, 8B aligned)
#define LOGITS_ELEMS (BATCH*SEQ*VOCAB)
// smem: Wsm[1024*32] + Hsm[16*1024] + Red[8*RSTRIDE] + embWsm[128*32]
#define SCAN_SMEM  ((1024*32 + 16*1024 + 8*RSTRIDE + 128*32) * 4)   // 229632 bytes

// ---------------- device scratch ----------------
__device__ float    g_hs[(size_t)SEQ * BATCH * HIDDEN];  // all h_t (128 MB)
__device__ unsigned g_bar[128];                          // group g counter at [g*32]: 1 line each

// ---------------- packed f32x2 helpers ----------------
typedef unsigned long long u64;

__device__ __forceinline__ u64 pack2(float x, float y) {
    u64 r;
    asm("mov.b64 %0, {%1, %2};" : "=l"(r) : "r"(__float_as_uint(x)), "r"(__float_as_uint(y)));
    return r;
}
__device__ __forceinline__ void unpack2(u64 v, float& x, float& y) {
    unsigned a, b;
    asm("mov.b64 {%0, %1}, %2;" : "=r"(a), "=r"(b) : "l"(v));
    x = __uint_as_float(a); y = __uint_as_float(b);
}
__device__ __forceinline__ void fma2(u64& acc, u64 a, u64 b) {
    asm("fma.rn.f32x2 %0, %1, %2, %0;" : "+l"(acc) : "l"(a), "l"(b));
}
__device__ __forceinline__ void add2(u64& acc, u64 v) {
    asm("add.rn.f32x2 %0, %0, %1;" : "+l"(acc) : "l"(v));
}
__device__ __forceinline__ unsigned ld_acquire(const unsigned* p) {
    unsigned v;
    asm volatile("ld.acquire.gpu.global.u32 %0, [%1];" : "=r"(v) : "l"(p) : "memory");
    return v;
}

// ================================================================================
// Round-7 k-loop (scan): lane = (bg = lane>>3, ng = lane&7); warp w covers k in
// [w*128, +128), lane computes 4 rows (bg*4..+4) x 4 cols (ng*4..+4).
// Hsm layout: float4 slot (row*256 + ((k>>2) ^ bg_of_row)), bg_of_row = row>>2.
// ================================================================================
__device__ __forceinline__ void kloop_partial(const float* __restrict__ Wsm,
                                              const float4* __restrict__ H4,
                                              int kbase, int bg, int ng, u64 acc[4][2])
{
    #pragma unroll 4
    for (int k = kbase; k < kbase + 128; k += 4) {
        const int kc = k >> 2;
        longlong2 wv0 = *(const longlong2*)&Wsm[(k + 0) * 32 + ng * 4];
        longlong2 wv1 = *(const longlong2*)&Wsm[(k + 1) * 32 + ng * 4];
        longlong2 wv2 = *(const longlong2*)&Wsm[(k + 2) * 32 + ng * 4];
        longlong2 wv3 = *(const longlong2*)&Wsm[(k + 3) * 32 + ng * 4];
        #pragma unroll
        for (int i = 0; i < 4; ++i) {
            float4 h4 = H4[(bg * 4 + i) * 256 + (kc ^ bg)];
            u64 ha = pack2(h4.x, h4.x);
            u64 hb = pack2(h4.y, h4.y);
            u64 hc = pack2(h4.z, h4.z);
            u64 hd = pack2(h4.w, h4.w);
            fma2(acc[i][0], ha, (u64)wv0.x);  fma2(acc[i][1], ha, (u64)wv0.y);
            fma2(acc[i][0], hb, (u64)wv1.x);  fma2(acc[i][1], hb, (u64)wv1.y);
            fma2(acc[i][0], hc, (u64)wv2.x);  fma2(acc[i][1], hc, (u64)wv2.y);
            fma2(acc[i][0], hd, (u64)wv3.x);  fma2(acc[i][1], hd, (u64)wv3.y);
        }
    }
}

// Per-warp staging of this warp's own k-slice: rows 0..15, cols [w*128, +128).
__device__ __forceinline__ void stage_own_slice(float4* __restrict__ H4,
                                                const float* __restrict__ src,
                                                int kc_l /* = w*32 + lane */)
{
    float4 v[16];
    #pragma unroll
    for (int j = 0; j < 16; ++j)
        v[j] = *(const float4*)&src[(size_t)j * 1024 + kc_l * 4];
    #pragma unroll
    for (int j = 0; j < 16; ++j)
        H4[j * 256 + (kc_l ^ (j >> 2))] = v[j];
    __syncwarp();
}

// ================================================================================
// Kernel 1: persistent RNN scan, single launch, t in [0, SEQ).
// Round-13 structure + PDL trigger. Final-h d_out write moved to finalize kernel.
// ================================================================================
__global__ void __launch_bounds__(256, 1)
rnn_scan_kernel(const int*   __restrict__ x,
                const float* __restrict__ h0,
                const float* __restrict__ emb,
                const float* __restrict__ W_hx,
                const float* __restrict__ b_hx,
                const float* __restrict__ W_hh)
{
    extern __shared__ float smem[];
    float*  Wsm    = smem;                       // [1024][32]
    float*  Hsm    = smem + 1024 * 32;           // [16][1024] swizzled float4
    float4* H4     = (float4*)Hsm;
    float*  Red    = Hsm + 16 * 1024;            // [8][RSTRIDE]
    float*  embWsm = Red + 8 * RSTRIDE;          // [128][32]
    __shared__ volatile int sflag;

    const int tid = threadIdx.x;
    const int cta = blockIdx.x;
    const int gb  = cta >> 5;          // batch group 0..3
    const int gn  = cta & 31;          // column slice 0..31
    const int b0  = gb * 16;
    const int n0  = gn * 32;

    if (tid == 0) {
        sflag = -1;
        cudaTriggerProgrammaticLaunchCompletion();   // release the logits launch
    }

    const int lane  = tid & 31;
    const int w     = tid >> 5;
    const int bg    = lane >> 3;
    const int ng    = lane & 7;
    const int kbase = w * 128;
    const int kc_l  = w * 32 + lane;
    const int o2    = tid * 2;
    const int rb    = o2 >> 5;         // batch row within group (0..15)
    const int rn    = o2 & 31;         // even col within slice

    // ---------------- Prologue: embWsm = emb @ W_hx[:, n0:+32] + b_hx ----------------
    for (int i = tid; i < 1024 * 8; i += 256) {
        int k = i >> 3, q = i & 7;
        *(float4*)&Wsm[k * 32 + q * 4] =
            *(const float4*)&W_hx[(size_t)k * 1024 + n0 + q * 4];
    }
    __syncthreads();
    for (int vg = 0; vg < 8; ++vg) {
        stage_own_slice(H4, &emb[(size_t)(vg * 16) * 1024], kc_l);
        float2 bb = *(const float2*)&b_hx[n0 + rn];
        u64 acc[4][2];
        #pragma unroll
        for (int i = 0; i < 4; ++i) { acc[i][0] = 0ull; acc[i][1] = 0ull; }
        kloop_partial(Wsm, H4, kbase, bg, ng, acc);
        #pragma unroll
        for (int i = 0; i < 4; ++i) {
            int o = (bg * 4 + i) * 32 + ng * 4;
            *(u64*)&Red[w * RSTRIDE + o]     = acc[i][0];
            *(u64*)&Red[w * RSTRIDE + o + 2] = acc[i][1];
        }
        __syncthreads();
        u64 s = *(const u64*)&Red[o2];
        #pragma unroll
        for (int ww = 1; ww < 8; ++ww)
            add2(s, *(const u64*)&Red[ww * RSTRIDE + o2]);
        float s0, s1;
        unpack2(s, s0, s1);
        *(float2*)&embWsm[(vg * 16 + rb) * 32 + rn] =
            make_float2(s0 + bb.x, s1 + bb.y);
        __syncthreads();   // Red reads done before next vg's writes
    }

    // Load W_hh slice (overwrites Wsm; prologue reads are sync'd above).
    for (int i = tid; i < 1024 * 8; i += 256) {
        int k = i >> 3, q = i & 7;
        *(float4*)&Wsm[k * 32 + q * 4] =
            *(const float4*)&W_hh[(size_t)k * 1024 + n0 + q * 4];
    }
    __syncthreads();

    // ---------------- Scan ----------------
    unsigned* gbar = &g_bar[gb * 32];   // one 128B line per group

    for (int t = 0; t < SEQ; ++t) {
        if (t > 0) {
            if (tid == 0) {
                unsigned tgt = 32u * (unsigned)t;
                while (ld_acquire(gbar) < tgt) { }
                sflag = t;
            }
            while (sflag < t) { }       // cheap SMEM spin
        }

        const float* hsrc = (t == 0)
            ? (h0 + (size_t)b0 * 1024)
            : (g_hs + (size_t)(t - 1) * (BATCH * HIDDEN) + (size_t)b0 * 1024);
        stage_own_slice(H4, hsrc, kc_l);

        int myx = x[(size_t)(b0 + rb) * SEQ + t];   // early issue; used post-kloop
        float2 e = *(const float2*)&embWsm[myx * 32 + rn];

        u64 acc[4][2];
        #pragma unroll
        for (int i = 0; i < 4; ++i) { acc[i][0] = 0ull; acc[i][1] = 0ull; }
        kloop_partial(Wsm, H4, kbase, bg, ng, acc);

        #pragma unroll
        for (int i = 0; i < 4; ++i) {
            int o = (bg * 4 + i) * 32 + ng * 4;
            *(u64*)&Red[w * RSTRIDE + o]     = acc[i][0];
            *(u64*)&Red[w * RSTRIDE + o + 2] = acc[i][1];
        }
        __syncthreads();                     // sync A: Red writes -> reduce reads

        u64 s = *(const u64*)&Red[o2];
        #pragma unroll
        for (int ww = 1; ww < 8; ++ww)
            add2(s, *(const u64*)&Red[ww * RSTRIDE + o2]);
        float s0, s1;
        unpack2(s, s0, s1);
        float r0 = tanhf(s0 + e.x);
        float r1 = tanhf(s1 + e.y);
        *(float2*)&g_hs[(size_t)t * (BATCH * HIDDEN) + (size_t)(b0 + rb) * 1024 + n0 + rn]
            = make_float2(r0, r1);

        __syncthreads();                     // sync B: all h stores HB tid0's release
        if (tid == 0) {
            __threadfence();
            atomicAdd(gbar, 1u);
        }
    }
}

// ================================================================================
// Kernel 2: logits. TWO timesteps per CTA, 8x8 thread tile, 2 CTAs/SM.
// PDL-launched: runs concurrently with the scan on the idle SMs. Wait uses
// DEFICIT-ADAPTIVE nanosleep backoff to keep acquire-poll traffic off the
// scan's latency-critical counter lines.
// ================================================================================
#define ASTRIDE 20

__global__ void __launch_bounds__(256, 2)
logits_kernel(const float* __restrict__ W_out,
              const float* __restrict__ b_out,
              float*       __restrict__ out)
{
    __shared__ float Asm[128 * ASTRIDE];
    __shared__ float Wsm[16 * 128];

    const int tid = threadIdx.x;

    // Wait until h_t for t0 = 2*bid and t1 = 2*bid+1 is published by ALL groups.
    if (tid == 0) {
        unsigned tgt = 32u * (unsigned)(blockIdx.x * 2 + 2);
        #pragma unroll
        for (int g = 0; g < 4; ++g) {
            unsigned cur;
            while ((cur = ld_acquire(&g_bar[g * 32])) < tgt) {
                unsigned deficit = tgt - cur;          // in arrivals (32 per step)
                __nanosleep(deficit > 128 ? 16384 : (deficit > 32 ? 4096 : 1024));
            }
        }
    }
    __syncthreads();

    const int rg  = tid >> 4;
    const int cg  = tid & 15;

    u64 acc[8][4];
    #pragma unroll
    for (int i = 0; i < 8; ++i)
        #pragma unroll
        for (int j = 0; j < 4; ++j) acc[i][j] = 0ull;

    const float* A = g_hs + (size_t)blockIdx.x * 2 * (BATCH * HIDDEN);
    const int ar = tid >> 1;
    const int ac = (tid & 1) * 8;

    for (int k0 = 0; k0 < 1024; k0 += 16) {
        __syncthreads();
        {
            float4 a0 = *(const float4*)&A[(size_t)ar * 1024 + k0 + ac];
            float4 a1 = *(const float4*)&A[(size_t)ar * 1024 + k0 + ac + 4];
            *(float4*)&Asm[ar * ASTRIDE + ac]     = a0;
            *(float4*)&Asm[ar * ASTRIDE + ac + 4] = a1;
        }
        {
            const float* src = &W_out[(size_t)(k0 + rg) * 128 + cg * 8];
            *(float4*)&Wsm[rg * 128 + cg * 8]     = *(const float4*)&src[0];
            *(float4*)&Wsm[rg * 128 + cg * 8 + 4] = *(const float4*)&src[4];
        }
        __syncthreads();
        #pragma unroll
        for (int kk = 0; kk < 16; ++kk) {
            const float* wrow = &Wsm[kk * 128 + cg * 8];
            u64 w0 = *(const u64*)&wrow[0];
            u64 w1 = *(const u64*)&wrow[2];
            u64 w2 = *(const u64*)&wrow[4];
            u64 w3 = *(const u64*)&wrow[6];
            #pragma unroll
            for (int i = 0; i < 8; ++i) {
                float a = Asm[(rg * 8 + i) * ASTRIDE + kk];
                u64 aa = pack2(a, a);
                fma2(acc[i][0], aa, w0);
                fma2(acc[i][1], aa, w1);
                fma2(acc[i][2], aa, w2);
                fma2(acc[i][3], aa, w3);
            }
        }
    }

    float4 bv0 = *(const float4*)&b_out[cg * 8];
    float4 bv1 = *(const float4*)&b_out[cg * 8 + 4];
    #pragma unroll
    for (int i = 0; i < 8; ++i) {
        int row = rg * 8 + i;
        int t   = blockIdx.x * 2 + (row >> 6);
        int b   = row & 63;
        float r0, r1, r2, r3, r4, r5, r6, r7;
        unpack2(acc[i][0], r0, r1);
        unpack2(acc[i][1], r2, r3);
        unpack2(acc[i][2], r4, r5);
        unpack2(acc[i][3], r6, r7);
        float* dst = &out[(size_t)b * (SEQ * VOCAB) + (size_t)t * VOCAB + cg * 8];
        *(float4*)dst       = make_float4(r0 + bv0.x, r1 + bv0.y, r2 + bv0.z, r3 + bv0.w);
        *(float4*)(dst + 4) = make_float4(r4 + bv1.x, r5 + bv1.y, r6 + bv1.z, r7 + bv1.w);
    }
}

// ================================================================================
// Kernel 3: finalize. Copies the final hidden state into d_out's tail and resets
// the scan counters for the next graph replay. Runs last (stream-ordered).
// ================================================================================
__global__ void __launch_bounds__(256)
finalize_kernel(float* __restrict__ d_out, int out_size)
{
    if (blockIdx.x == 0 && threadIdx.x < 128) g_bar[threadIdx.x] = 0u;
    if (out_size >= LOGITS_ELEMS + BATCH * HIDDEN) {
        int idx = (blockIdx.x * 256 + threadIdx.x) * 4;   // 16384 float4s
        const float4* src = (const float4*)&g_hs[(size_t)(SEQ - 1) * (BATCH * HIDDEN)];
        *(float4*)&d_out[(size_t)LOGITS_ELEMS + idx] = src[idx >> 2];
    }
}

// ================================================================================
extern "C" void kernel_launch(void* const* d_in, const int* in_sizes, int n_in,
                              void* d_out, int out_size)
{
    const int*   x     = (const int*)  d_in[0];
    const float* h     = (const float*)d_in[1];
    const float* emb   = (const float*)d_in[2];
    const float* W_hx  = (const float*)d_in[3];
    const float* b_hx  = (const float*)d_in[4];
    const float* W_hh  = (const float*)d_in[5];
    const float* W_out = (const float*)d_in[6];
    const float* b_out = (const float*)d_in[7];
    float*       out   = (float*)d_out;
    (void)in_sizes; (void)n_in;

    cudaFuncSetAttribute(rnn_scan_kernel,
                         cudaFuncAttributeMaxDynamicSharedMemorySize, SCAN_SMEM);

    rnn_scan_kernel<<<128, 256, SCAN_SMEM>>>(x, h, emb, W_hx, b_hx, W_hh);

    // Logits with programmatic dependent launch: overlaps the scan.
    {
        cudaLaunchConfig_t cfg = {};
        cfg.gridDim       = dim3(SEQ / 2);
        cfg.blockDim      = dim3(256);
        cfg.dynamicSmemBytes = 0;
        cfg.stream        = 0;
        cudaLaunchAttribute attrs[1];
        attrs[0].id = cudaLaunchAttributeProgrammaticStreamSerialization;
        attrs[0].val.programmaticStreamSerializationAllowed = 1;
        cfg.attrs    = attrs;
        cfg.numAttrs = 1;
        cudaLaunchKernelEx(&cfg, logits_kernel, W_out, b_out, out);
    }

    finalize_kernel<<<64, 256>>>(out, out_size);
}

// round 17
// speedup vs baseline: 1.0207x; 1.0207x over previous
#include <cuda_runtime.h>
#include <cuda_bf16.h>
#include <math.h>

#define VOCAB   128
#define HIDDEN  1024
#define BATCH   64
#define SEQ     512

#define RSTRIDE 520    // reduce-buffer warp stride (floats, 8B aligned)
#define LOGITS_ELEMS (BATCH*SEQ*VOCAB)
// smem: Wsm[1024*32] + Hsm[16*1024] + Red[8*RSTRIDE] + embWsm[128*32]
#define SCAN_SMEM  ((1024*32 + 16*1024 + 8*RSTRIDE + 128*32) * 4)   // 229632 bytes

// Logits decomposition: coarse 2-t blocks for t < T_SPLIT, fine (t, vocab-half)
// blocks for the tail (released near scan end; small => short tail latency).
#define T_SPLIT        448
#define COARSE_BLOCKS  (T_SPLIT / 2)                  // 224
#define FINE_BLOCKS    ((SEQ - T_SPLIT) * 2)          // 128
#define LOGITS_GRID    (COARSE_BLOCKS + FINE_BLOCKS)  // 352

// ---------------- device scratch ----------------
__device__ float    g_hs[(size_t)SEQ * BATCH * HIDDEN];  // all h_t (128 MB)
__device__ unsigned g_bar[128];                          // group g counter at [g*32]

// ---------------- packed f32x2 helpers ----------------
typedef unsigned long long u64;

__device__ __forceinline__ u64 pack2(float x, float y) {
    u64 r;
    asm("mov.b64 %0, {%1, %2};" : "=l"(r) : "r"(__float_as_uint(x)), "r"(__float_as_uint(y)));
    return r;
}
__device__ __forceinline__ void unpack2(u64 v, float& x, float& y) {
    unsigned a, b;
    asm("mov.b64 {%0, %1}, %2;" : "=r"(a), "=r"(b) : "l"(v));
    x = __uint_as_float(a); y = __uint_as_float(b);
}
__device__ __forceinline__ void fma2(u64& acc, u64 a, u64 b) {
    asm("fma.rn.f32x2 %0, %1, %2, %0;" : "+l"(acc) : "l"(a), "l"(b));
}
__device__ __forceinline__ void add2(u64& acc, u64 v) {
    asm("add.rn.f32x2 %0, %0, %1;" : "+l"(acc) : "l"(v));
}
__device__ __forceinline__ unsigned ld_acquire(const unsigned* p) {
    unsigned v;
    asm volatile("ld.acquire.gpu.global.u32 %0, [%1];" : "=r"(v) : "l"(p) : "memory");
    return v;
}
// Wait until all 4 group counters reach 32*steps (gentle fixed backoff).
__device__ __forceinline__ void wait_steps(unsigned steps) {
    unsigned tgt = 32u * steps;
    #pragma unroll
    for (int g = 0; g < 4; ++g)
        while (ld_acquire(&g_bar[g * 32]) < tgt) __nanosleep(256);
}

// ================================================================================
// Scan k-loop (round-7): lane = (bg = lane>>3, ng = lane&7); warp w covers k in
// [w*128, +128), lane computes 4 rows x 4 cols.
// Hsm layout: float4 slot (row*256 + ((k>>2) ^ (row>>2))).
// ================================================================================
__device__ __forceinline__ void kloop_partial(const float* __restrict__ Wsm,
                                              const float4* __restrict__ H4,
                                              int kbase, int bg, int ng, u64 acc[4][2])
{
    #pragma unroll 4
    for (int k = kbase; k < kbase + 128; k += 4) {
        const int kc = k >> 2;
        longlong2 wv0 = *(const longlong2*)&Wsm[(k + 0) * 32 + ng * 4];
        longlong2 wv1 = *(const longlong2*)&Wsm[(k + 1) * 32 + ng * 4];
        longlong2 wv2 = *(const longlong2*)&Wsm[(k + 2) * 32 + ng * 4];
        longlong2 wv3 = *(const longlong2*)&Wsm[(k + 3) * 32 + ng * 4];
        #pragma unroll
        for (int i = 0; i < 4; ++i) {
            float4 h4 = H4[(bg * 4 + i) * 256 + (kc ^ bg)];
            u64 ha = pack2(h4.x, h4.x);
            u64 hb = pack2(h4.y, h4.y);
            u64 hc = pack2(h4.z, h4.z);
            u64 hd = pack2(h4.w, h4.w);
            fma2(acc[i][0], ha, (u64)wv0.x);  fma2(acc[i][1], ha, (u64)wv0.y);
            fma2(acc[i][0], hb, (u64)wv1.x);  fma2(acc[i][1], hb, (u64)wv1.y);
            fma2(acc[i][0], hc, (u64)wv2.x);  fma2(acc[i][1], hc, (u64)wv2.y);
            fma2(acc[i][0], hd, (u64)wv3.x);  fma2(acc[i][1], hd, (u64)wv3.y);
        }
    }
}

// Per-warp staging of this warp's own k-slice.
__device__ __forceinline__ void stage_own_slice(float4* __restrict__ H4,
                                                const float* __restrict__ src,
                                                int kc_l)
{
    float4 v[16];
    #pragma unroll
    for (int j = 0; j < 16; ++j)
        v[j] = *(const float4*)&src[(size_t)j * 1024 + kc_l * 4];
    #pragma unroll
    for (int j = 0; j < 16; ++j)
        H4[j * 256 + (kc_l ^ (j >> 2))] = v[j];
    __syncwarp();
}

// ================================================================================
// Kernel 1: persistent RNN scan (identical to round-15/16 best).
// ================================================================================
__global__ void __launch_bounds__(256, 1)
rnn_scan_kernel(const int*   __restrict__ x,
                const float* __restrict__ h0,
                const float* __restrict__ emb,
                const float* __restrict__ W_hx,
                const float* __restrict__ b_hx,
                const float* __restrict__ W_hh)
{
    extern __shared__ float smem[];
    float*  Wsm    = smem;
    float*  Hsm    = smem + 1024 * 32;
    float4* H4     = (float4*)Hsm;
    float*  Red    = Hsm + 16 * 1024;
    float*  embWsm = Red + 8 * RSTRIDE;
    __shared__ volatile int sflag;

    const int tid = threadIdx.x;
    const int cta = blockIdx.x;
    const int gb  = cta >> 5;
    const int gn  = cta & 31;
    const int b0  = gb * 16;
    const int n0  = gn * 32;

    if (tid == 0) {
        sflag = -1;
        cudaTriggerProgrammaticLaunchCompletion();
    }

    const int lane  = tid & 31;
    const int w     = tid >> 5;
    const int bg    = lane >> 3;
    const int ng    = lane & 7;
    const int kbase = w * 128;
    const int kc_l  = w * 32 + lane;
    const int o2    = tid * 2;
    const int rb    = o2 >> 5;
    const int rn    = o2 & 31;

    // Prologue: embWsm = emb @ W_hx[:, n0:+32] + b_hx
    for (int i = tid; i < 1024 * 8; i += 256) {
        int k = i >> 3, q = i & 7;
        *(float4*)&Wsm[k * 32 + q * 4] =
            *(const float4*)&W_hx[(size_t)k * 1024 + n0 + q * 4];
    }
    __syncthreads();
    for (int vg = 0; vg < 8; ++vg) {
        stage_own_slice(H4, &emb[(size_t)(vg * 16) * 1024], kc_l);
        float2 bb = *(const float2*)&b_hx[n0 + rn];
        u64 acc[4][2];
        #pragma unroll
        for (int i = 0; i < 4; ++i) { acc[i][0] = 0ull; acc[i][1] = 0ull; }
        kloop_partial(Wsm, H4, kbase, bg, ng, acc);
        #pragma unroll
        for (int i = 0; i < 4; ++i) {
            int o = (bg * 4 + i) * 32 + ng * 4;
            *(u64*)&Red[w * RSTRIDE + o]     = acc[i][0];
            *(u64*)&Red[w * RSTRIDE + o + 2] = acc[i][1];
        }
        __syncthreads();
        u64 s = *(const u64*)&Red[o2];
        #pragma unroll
        for (int ww = 1; ww < 8; ++ww)
            add2(s, *(const u64*)&Red[ww * RSTRIDE + o2]);
        float s0, s1;
        unpack2(s, s0, s1);
        *(float2*)&embWsm[(vg * 16 + rb) * 32 + rn] =
            make_float2(s0 + bb.x, s1 + bb.y);
        __syncthreads();
    }

    // Load W_hh slice.
    for (int i = tid; i < 1024 * 8; i += 256) {
        int k = i >> 3, q = i & 7;
        *(float4*)&Wsm[k * 32 + q * 4] =
            *(const float4*)&W_hh[(size_t)k * 1024 + n0 + q * 4];
    }
    __syncthreads();

    unsigned* gbar = &g_bar[gb * 32];

    for (int t = 0; t < SEQ; ++t) {
        if (t > 0) {
            if (tid == 0) {
                unsigned tgt = 32u * (unsigned)t;
                while (ld_acquire(gbar) < tgt) { }
                sflag = t;
            }
            while (sflag < t) { }
        }

        const float* hsrc = (t == 0)
            ? (h0 + (size_t)b0 * 1024)
            : (g_hs + (size_t)(t - 1) * (BATCH * HIDDEN) + (size_t)b0 * 1024);
        stage_own_slice(H4, hsrc, kc_l);

        int myx = x[(size_t)(b0 + rb) * SEQ + t];
        float2 e = *(const float2*)&embWsm[myx * 32 + rn];

        u64 acc[4][2];
        #pragma unroll
        for (int i = 0; i < 4; ++i) { acc[i][0] = 0ull; acc[i][1] = 0ull; }
        kloop_partial(Wsm, H4, kbase, bg, ng, acc);

        #pragma unroll
        for (int i = 0; i < 4; ++i) {
            int o = (bg * 4 + i) * 32 + ng * 4;
            *(u64*)&Red[w * RSTRIDE + o]     = acc[i][0];
            *(u64*)&Red[w * RSTRIDE + o + 2] = acc[i][1];
        }
        __syncthreads();

        u64 s = *(const u64*)&Red[o2];
        #pragma unroll
        for (int ww = 1; ww < 8; ++ww)
            add2(s, *(const u64*)&Red[ww * RSTRIDE + o2]);
        float s0, s1;
        unpack2(s, s0, s1);
        float r0 = tanhf(s0 + e.x);
        float r1 = tanhf(s1 + e.y);
        *(float2*)&g_hs[(size_t)t * (BATCH * HIDDEN) + (size_t)(b0 + rb) * 1024 + n0 + rn]
            = make_float2(r0, r1);

        __syncthreads();
        if (tid == 0) {
            __threadfence();
            atomicAdd(gbar, 1u);
        }
    }
}

// ================================================================================
// Kernel 2: logits, two-resolution, PDL-launched to overlap the scan.
// bid <  COARSE_BLOCKS : 2 timesteps x full vocab (128x128 tile, efficient body)
// bid >= COARSE_BLOCKS : 1 timestep x vocab-half (64x64 tile, short-latency tail)
// ================================================================================
#define ASTRIDE 20

__global__ void __launch_bounds__(256, 2)
logits_kernel(const float* __restrict__ W_out,
              const float* __restrict__ b_out,
              float*       __restrict__ out)
{
    __shared__ float Asm[128 * ASTRIDE];
    __shared__ float Wsm[16 * 128];

    const int tid = threadIdx.x;
    const int bid = blockIdx.x;

    if (bid < COARSE_BLOCKS) {
        // ---------------- coarse: 2 timesteps, full vocab ----------------
        if (tid == 0) wait_steps((unsigned)(bid * 2 + 2));
        __syncthreads();

        const int rg  = tid >> 4;
        const int cg  = tid & 15;

        u64 acc[8][4];
        #pragma unroll
        for (int i = 0; i < 8; ++i)
            #pragma unroll
            for (int j = 0; j < 4; ++j) acc[i][j] = 0ull;

        const float* A = g_hs + (size_t)bid * 2 * (BATCH * HIDDEN);
        const int ar = tid >> 1;
        const int ac = (tid & 1) * 8;

        for (int k0 = 0; k0 < 1024; k0 += 16) {
            __syncthreads();
            {
                float4 a0 = *(const float4*)&A[(size_t)ar * 1024 + k0 + ac];
                float4 a1 = *(const float4*)&A[(size_t)ar * 1024 + k0 + ac + 4];
                *(float4*)&Asm[ar * ASTRIDE + ac]     = a0;
                *(float4*)&Asm[ar * ASTRIDE + ac + 4] = a1;
            }
            {
                const float* src = &W_out[(size_t)(k0 + rg) * 128 + cg * 8];
                *(float4*)&Wsm[rg * 128 + cg * 8]     = *(const float4*)&src[0];
                *(float4*)&Wsm[rg * 128 + cg * 8 + 4] = *(const float4*)&src[4];
            }
            __syncthreads();
            #pragma unroll
            for (int kk = 0; kk < 16; ++kk) {
                const float* wrow = &Wsm[kk * 128 + cg * 8];
                u64 w0 = *(const u64*)&wrow[0];
                u64 w1 = *(const u64*)&wrow[2];
                u64 w2 = *(const u64*)&wrow[4];
                u64 w3 = *(const u64*)&wrow[6];
                #pragma unroll
                for (int i = 0; i < 8; ++i) {
                    float a = Asm[(rg * 8 + i) * ASTRIDE + kk];
                    u64 aa = pack2(a, a);
                    fma2(acc[i][0], aa, w0);
                    fma2(acc[i][1], aa, w1);
                    fma2(acc[i][2], aa, w2);
                    fma2(acc[i][3], aa, w3);
                }
            }
        }

        float4 bv0 = *(const float4*)&b_out[cg * 8];
        float4 bv1 = *(const float4*)&b_out[cg * 8 + 4];
        #pragma unroll
        for (int i = 0; i < 8; ++i) {
            int row = rg * 8 + i;
            int t   = bid * 2 + (row >> 6);
            int b   = row & 63;
            float r0, r1, r2, r3, r4, r5, r6, r7;
            unpack2(acc[i][0], r0, r1);
            unpack2(acc[i][1], r2, r3);
            unpack2(acc[i][2], r4, r5);
            unpack2(acc[i][3], r6, r7);
            float* dst = &out[(size_t)b * (SEQ * VOCAB) + (size_t)t * VOCAB + cg * 8];
            *(float4*)dst       = make_float4(r0 + bv0.x, r1 + bv0.y, r2 + bv0.z, r3 + bv0.w);
            *(float4*)(dst + 4) = make_float4(r4 + bv1.x, r5 + bv1.y, r6 + bv1.z, r7 + bv1.w);
        }
    } else {
        // ---------------- fine: 1 timestep, half vocab (64 rows x 64 cols) --------
        const int fb = bid - COARSE_BLOCKS;
        const int t  = T_SPLIT + (fb >> 1);
        const int vh = fb & 1;            // vocab half 0..1
        const int v0 = vh * 64;

        if (tid == 0) wait_steps((unsigned)(t + 1));
        __syncthreads();

        const int rg = tid >> 4;          // 0..15 -> rows rg*4..+4
        const int cg = tid & 15;          // 0..15 -> cols cg*4..+4

        u64 acc[4][2];
        #pragma unroll
        for (int i = 0; i < 4; ++i) { acc[i][0] = 0ull; acc[i][1] = 0ull; }

        const float* A = g_hs + (size_t)t * (BATCH * HIDDEN);
        const int ar = tid >> 2;          // 0..63
        const int ac = (tid & 3) * 4;     // 0,4,8,12

        for (int k0 = 0; k0 < 1024; k0 += 16) {
            __syncthreads();
            {
                float4 a0 = *(const float4*)&A[(size_t)ar * 1024 + k0 + ac];
                *(float4*)&Asm[ar * ASTRIDE + ac] = a0;
            }
            {
                int wr = tid >> 4;        // 0..15 (k row)
                int wc = (tid & 15) * 4;  // 0..60
                *(float4*)&Wsm[wr * 64 + wc] =
                    *(const float4*)&W_out[(size_t)(k0 + wr) * 128 + v0 + wc];
            }
            __syncthreads();
            #pragma unroll
            for (int kk = 0; kk < 16; ++kk) {
                const float* wrow = &Wsm[kk * 64 + cg * 4];
                u64 w0 = *(const u64*)&wrow[0];
                u64 w1 = *(const u64*)&wrow[2];
                #pragma unroll
                for (int i = 0; i < 4; ++i) {
                    float a = Asm[(rg * 4 + i) * ASTRIDE + kk];
                    u64 aa = pack2(a, a);
                    fma2(acc[i][0], aa, w0);
                    fma2(acc[i][1], aa, w1);
                }
            }
        }

        float4 bv = *(const float4*)&b_out[v0 + cg * 4];
        #pragma unroll
        for (int i = 0; i < 4; ++i) {
            int b = rg * 4 + i;           // batch row
            float r0, r1, r2, r3;
            unpack2(acc[i][0], r0, r1);
            unpack2(acc[i][1], r2, r3);
            float* dst = &out[(size_t)b * (SEQ * VOCAB) + (size_t)t * VOCAB + v0 + cg * 4];
            *(float4*)dst = make_float4(r0 + bv.x, r1 + bv.y, r2 + bv.z, r3 + bv.w);
        }
    }
}

// ================================================================================
// Kernel 3: finalize. Copies the final hidden state into d_out's tail and resets
// the scan counters for the next graph replay. Runs last (stream-ordered).
// ================================================================================
__global__ void __launch_bounds__(256)
finalize_kernel(float* __restrict__ d_out, int out_size)
{
    if (blockIdx.x == 0 && threadIdx.x < 128) g_bar[threadIdx.x] = 0u;
    if (out_size >= LOGITS_ELEMS + BATCH * HIDDEN) {
        int idx = (blockIdx.x * 256 + threadIdx.x) * 4;   // 16384 float4s
        const float4* src = (const float4*)&g_hs[(size_t)(SEQ - 1) * (BATCH * HIDDEN)];
        *(float4*)&d_out[(size_t)LOGITS_ELEMS + idx] = src[idx >> 2];
    }
}

// ================================================================================
extern "C" void kernel_launch(void* const* d_in, const int* in_sizes, int n_in,
                              void* d_out, int out_size)
{
    const int*   x     = (const int*)  d_in[0];
    const float* h     = (const float*)d_in[1];
    const float* emb   = (const float*)d_in[2];
    const float* W_hx  = (const float*)d_in[3];
    const float* b_hx  = (const float*)d_in[4];
    const float* W_hh  = (const float*)d_in[5];
    const float* W_out = (const float*)d_in[6];
    const float* b_out = (const float*)d_in[7];
    float*       out   = (float*)d_out;
    (void)in_sizes; (void)n_in;

    cudaFuncSetAttribute(rnn_scan_kernel,
                         cudaFuncAttributeMaxDynamicSharedMemorySize, SCAN_SMEM);

    rnn_scan_kernel<<<128, 256, SCAN_SMEM>>>(x, h, emb, W_hx, b_hx, W_hh);

    // Logits with programmatic dependent launch: overlaps the scan.
    {
        cudaLaunchConfig_t cfg = {};
        cfg.gridDim       = dim3(LOGITS_GRID);
        cfg.blockDim      = dim3(256);
        cfg.dynamicSmemBytes = 0;
        cfg.stream        = 0;
        cudaLaunchAttribute attrs[1];
        attrs[0].id = cudaLaunchAttributeProgrammaticStreamSerialization;
        attrs[0].val.programmaticStreamSerializationAllowed = 1;
        cfg.attrs    = attrs;
        cfg.numAttrs = 1;
        cudaLaunchKernelEx(&cfg, logits_kernel, W_out, b_out, out);
    }

    finalize_kernel<<<64, 256>>>(out, out_size);
}